// round 8
// baseline (speedup 1.0000x reference)
#include <cuda_runtime.h>
#include <cuda_bf16.h>
#include <cstdint>

// ---------------- problem constants ----------------
#define BB 8
#define NN 2048
#define KNBR 20
#define NPTS (BB*NN)          // 16384
#define EDGE_CNT (NPTS*KNBR)  // 327680
#define KPMAX 384             // max padded split-K (3*128)
#define NEGINF __int_as_float(0xff800000)

// ---------------- device scratch (static, no runtime alloc) ----------------
__device__ float g_D[(size_t)NN*NN];           // 16 MB: ONE batch of pairwise scores (L2-resident)
__device__ int   g_idx[NPTS*KNBR];
__device__ float g_xx[NPTS];
__device__ __nv_bfloat16 g_Acat[(size_t)NPTS*KPMAX];  // [xh|xh|xl]
__device__ __nv_bfloat16 g_Bcat[(size_t)NPTS*KPMAX];  // [xh|xl|xh]
__device__ __nv_bfloat16 g_Wp[(size_t)512*KPMAX];     // [Wh|Wl|Wh] per out-channel
__device__ float g_uv[(size_t)NPTS*512];
__device__ float g_hmax[(size_t)NPTS*256];
__device__ float g_hmin[(size_t)NPTS*256];
__device__ float g_xa[(size_t)NPTS*64];
__device__ float g_xb[(size_t)NPTS*128];
__device__ float g_xc[(size_t)NPTS*256];
__device__ float g_psum[512*256];
__device__ float g_psq [512*256];
__device__ float g_scale[256];
__device__ float g_shift[256];
__device__ float g_pool[BB*256];

// ---------------- hi/lo split pack of activations ----------------
__global__ void prep_cat(const float* __restrict__ x, __nv_bfloat16* __restrict__ Ac,
                         __nv_bfloat16* __restrict__ Bc, int C, int Kp)
{
    long long i = (long long)blockIdx.x * 256 + threadIdx.x;
    long long total = (long long)NPTS * Kp;
    if (i >= total) return;
    int n = (int)(i / Kp);
    int q = (int)(i - (long long)n * Kp);
    __nv_bfloat16 a, b;
    if (q < 3 * C) {
        int seg = q / C, c = q - seg * C;
        float v = x[(size_t)n * C + c];
        __nv_bfloat16 hi = __float2bfloat16(v);
        __nv_bfloat16 lo = __float2bfloat16(v - __bfloat162float(hi));
        if (seg == 0)      { a = hi; b = hi; }
        else if (seg == 1) { a = hi; b = lo; }
        else               { a = lo; b = hi; }
    } else {
        a = __float2bfloat16(0.f); b = a;
    }
    Ac[i] = a; Bc[i] = b;
}

// ---------------- weight pack: Wp[j][q], segs [Wh|Wl|Wh] of (W1-W2 | W2) ----------------
__global__ void wpack(const float* __restrict__ w, __nv_bfloat16* __restrict__ Bp,
                      int C, int O, int Kp)
{
    int i = blockIdx.x * 256 + threadIdx.x;
    if (i >= 2 * O * Kp) return;
    int j = i / Kp, q = i - j * Kp;
    __nv_bfloat16 outv = __float2bfloat16(0.f);
    if (q < 3 * C) {
        int seg = q / C, c = q - seg * C;
        float base = (j < O) ? (w[j * 2 * C + c] - w[j * 2 * C + C + c])
                             : w[(j - O) * 2 * C + C + c];
        __nv_bfloat16 hi = __float2bfloat16(base);
        outv = (seg == 1) ? __float2bfloat16(base - __bfloat162float(hi)) : hi;
    }
    Bp[i] = outv;
}

// ---------------- squared norms (exact fp32) ----------------
__global__ void xx_kernel(const float* __restrict__ x, float* __restrict__ xx, int C)
{
    int n = blockIdx.x * 256 + threadIdx.x;
    if (n >= NPTS) return;
    const float* p = x + (size_t)n * C;
    float s = 0.f;
    for (int c = 0; c < C; ++c) s = fmaf(p[c], p[c], s);
    xx[n] = s;
}

// ---------------- HMMA helpers ----------------
__device__ __forceinline__ uint32_t smem_u32(const void* p){
    uint32_t r; asm("{ .reg .u64 t; cvta.to.shared.u64 t, %1; cvt.u32.u64 %0, t; }" : "=r"(r) : "l"(p)); return r;
}
__device__ __forceinline__ void ldm_x4(uint32_t& r0, uint32_t& r1, uint32_t& r2, uint32_t& r3, uint32_t a){
    asm volatile("ldmatrix.sync.aligned.m8n8.x4.shared.b16 {%0,%1,%2,%3}, [%4];"
                 : "=r"(r0), "=r"(r1), "=r"(r2), "=r"(r3) : "r"(a));
}
__device__ __forceinline__ void ldm_x2(uint32_t& r0, uint32_t& r1, uint32_t a){
    asm volatile("ldmatrix.sync.aligned.m8n8.x2.shared.b16 {%0,%1}, [%2];"
                 : "=r"(r0), "=r"(r1) : "r"(a));
}
__device__ __forceinline__ void mma16816(float* c, uint32_t a0, uint32_t a1, uint32_t a2, uint32_t a3,
                                         uint32_t b0, uint32_t b1){
    asm volatile("mma.sync.aligned.m16n8k16.row.col.f32.bf16.bf16.f32 "
                 "{%0,%1,%2,%3}, {%4,%5,%6,%7}, {%8,%9}, {%0,%1,%2,%3};"
                 : "+f"(c[0]), "+f"(c[1]), "+f"(c[2]), "+f"(c[3])
                 : "r"(a0), "r"(a1), "r"(a2), "r"(a3), "r"(b0), "r"(b1));
}
__device__ __forceinline__ uint32_t swadr(uint32_t base, int r, int c, int CPR){
    int sc = (c & ~7) | ((c ^ r) & 7);
    return base + (uint32_t)((r * CPR + sc) << 4);
}

// ---------------- HMMA GEMM-NT, 128x128 CTA tile, full-K resident, direct register stores ----------------
// MODE 1 (dist): Out = 2*acc - aux[col]
// MODE 0 (uv):   Out = acc + (col<Obias ? aux[col] : 0)
template<int MODE>
__global__ __launch_bounds__(256, 2)
void mma_nt(const __nv_bfloat16* __restrict__ A, const __nv_bfloat16* __restrict__ Bm,
            const float* __restrict__ aux, float* __restrict__ Out,
            int Kp, int ldOut, int Obias)
{
    extern __shared__ char smem[];
    __shared__ float scol[128];

    const int tid = threadIdx.x, wid = tid >> 5, lane = tid & 31;
    const int colBase = blockIdx.x * 128, rowBase = blockIdx.y * 128;
    const int CPR = Kp >> 3;

    char* smA = smem;
    char* smB = smem + (size_t)256 * Kp;
    const uint32_t uA = smem_u32(smA), uB = smem_u32(smB);

    if (tid < 128) {
        if (MODE == 1) scol[tid] = aux[colBase + tid];
        else { int c = colBase + tid; scol[tid] = (c < Obias) ? aux[c] : 0.f; }
    }

    const __nv_bfloat16* gA = A + (size_t)rowBase * Kp;
    const __nv_bfloat16* gB = Bm + (size_t)colBase * Kp;
    int nchunks = 128 * CPR;
    for (int i = tid; i < nchunks; i += 256) {
        int r = i / CPR, c = i - r * CPR;
        uint32_t off = (uint32_t)((r * CPR + ((c & ~7) | ((c ^ r) & 7))) << 4);
        uint4 va = *reinterpret_cast<const uint4*>(gA + (size_t)r * Kp + c * 8);
        uint4 vb = *reinterpret_cast<const uint4*>(gB + (size_t)r * Kp + c * 8);
        *reinterpret_cast<uint4*>(smA + off) = va;
        *reinterpret_cast<uint4*>(smB + off) = vb;
    }
    __syncthreads();

    const int wm = wid & 1, wn = wid >> 1;
    const int mW = wm * 64, nW = wn * 32;

    float acc[4][4][4];
#pragma unroll
    for (int i = 0; i < 4; ++i)
#pragma unroll
        for (int j = 0; j < 4; ++j)
#pragma unroll
            for (int q = 0; q < 4; ++q) acc[i][j][q] = 0.f;

    const int aRow = lane & 15, aCH = lane >> 4;
    const int bRow = lane & 7,  bCH = (lane >> 3) & 1;

    for (int k0 = 0; k0 < Kp; k0 += 16) {
        int cbase = k0 >> 3;
        uint32_t a0[4], a1[4], a2[4], a3[4];
#pragma unroll
        for (int mi = 0; mi < 4; ++mi) {
            int r = mW + mi * 16 + aRow;
            ldm_x4(a0[mi], a1[mi], a2[mi], a3[mi], swadr(uA, r, cbase + aCH, CPR));
        }
        uint32_t b0[4], b1[4];
#pragma unroll
        for (int ni = 0; ni < 4; ++ni) {
            int r = nW + ni * 8 + bRow;
            ldm_x2(b0[ni], b1[ni], swadr(uB, r, cbase + bCH, CPR));
        }
#pragma unroll
        for (int mi = 0; mi < 4; ++mi)
#pragma unroll
            for (int ni = 0; ni < 4; ++ni)
                mma16816(acc[mi][ni], a0[mi], a1[mi], a2[mi], a3[mi], b0[ni], b1[ni]);
    }

    // direct register epilogue: 4-lane groups write 32B-contiguous float2s
    const int tq = lane >> 2, tr = lane & 3;
#pragma unroll
    for (int mi = 0; mi < 4; ++mi) {
#pragma unroll
        for (int q2 = 0; q2 < 2; ++q2) {
            int row = rowBase + mW + mi * 16 + tq + q2 * 8;
            float* dst = Out + (size_t)row * ldOut + colBase + nW + tr * 2;
#pragma unroll
            for (int ni = 0; ni < 4; ++ni) {
                int cl = nW + ni * 8 + tr * 2;
                float2 v;
                if (MODE == 1) {
                    v.x = 2.f * acc[mi][ni][2 * q2 + 0] - scol[cl];
                    v.y = 2.f * acc[mi][ni][2 * q2 + 1] - scol[cl + 1];
                } else {
                    v.x = acc[mi][ni][2 * q2 + 0] + scol[cl];
                    v.y = acc[mi][ni][2 * q2 + 1] + scol[cl + 1];
                }
                *reinterpret_cast<float2*>(dst + ni * 8) = v;
            }
        }
    }
}

// ---------------- hierarchical top-k: warp-local top-20, then merge ----------------
__global__ __launch_bounds__(256, 4)
void topk_kernel(const float* __restrict__ D, int* __restrict__ out, int gbase)
{
    __shared__ float swv[160];
    __shared__ int   swi[160];

    const int q = blockIdx.x, tid = threadIdx.x;
    const int wid = tid >> 5, lane = tid & 31;
    const float* row = D + (size_t)q * NN;

    float v[8];
    int cbase = wid * 256 + lane;
#pragma unroll
    for (int j = 0; j < 8; ++j) v[j] = row[cbase + j * 32];

    float lm = NEGINF; int lj = 0;
#pragma unroll
    for (int j = 0; j < 8; ++j) if (v[j] > lm) { lm = v[j]; lj = j; }

    for (int it = 0; it < KNBR; ++it) {
        float m = lm; int mi = cbase + lj * 32;
#pragma unroll
        for (int off = 16; off; off >>= 1) {
            float ov = __shfl_down_sync(0xffffffffu, m, off);
            int   oi = __shfl_down_sync(0xffffffffu, mi, off);
            if (ov > m) { m = ov; mi = oi; }
        }
        m  = __shfl_sync(0xffffffffu, m, 0);
        mi = __shfl_sync(0xffffffffu, mi, 0);
        if (lane == 0) { swv[wid * 20 + it] = m; swi[wid * 20 + it] = mi; }
        if (cbase + lj * 32 == mi) {
            v[lj] = NEGINF;
            lm = NEGINF; lj = 0;
#pragma unroll
            for (int j = 0; j < 8; ++j) if (v[j] > lm) { lm = v[j]; lj = j; }
        }
    }
    __syncthreads();

    if (wid == 0) {
        float c[5]; int ci[5];
#pragma unroll
        for (int j = 0; j < 5; ++j) { c[j] = swv[lane * 5 + j]; ci[j] = swi[lane * 5 + j]; }
        float lm2 = NEGINF; int lj2 = 0;
#pragma unroll
        for (int j = 0; j < 5; ++j) if (c[j] > lm2) { lm2 = c[j]; lj2 = j; }

        for (int it = 0; it < KNBR; ++it) {
            float m = lm2; int mi = ci[lj2];
#pragma unroll
            for (int off = 16; off; off >>= 1) {
                float ov = __shfl_down_sync(0xffffffffu, m, off);
                int   oi = __shfl_down_sync(0xffffffffu, mi, off);
                if (ov > m) { m = ov; mi = oi; }
            }
            m  = __shfl_sync(0xffffffffu, m, 0);
            mi = __shfl_sync(0xffffffffu, mi, 0);
            if (lane == 0) out[q * KNBR + it] = gbase + mi;
            if (ci[lj2] == mi && lm2 == m) {
                c[lj2] = NEGINF;
                lm2 = NEGINF; lj2 = 0;
#pragma unroll
                for (int j = 0; j < 5; ++j) if (c[j] > lm2) { lm2 = c[j]; lj2 = j; }
            }
        }
    }
}

// ---------------- BN stats + per-(n,o) hmax/hmin over edges (single gather pass) ----------------
__global__ __launch_bounds__(256)
void stats_kernel(const float* __restrict__ uv, const int* __restrict__ idx,
                  float* __restrict__ psum, float* __restrict__ psq,
                  float* __restrict__ hmax, float* __restrict__ hmin, int O)
{
    __shared__ int sidx[4][KNBR];
    __shared__ float sred[256], sred2[256];

    const int tid = threadIdx.x;
    const int og = tid & (O - 1);
    const int qs = tid / O;
    const int grp = 256 / O;
    const int twoO = 2 * O;
    const int q0 = blockIdx.x * 32;

    float s = 0.f, s2 = 0.f;
    for (int rq = 0; rq < 32; rq += grp) {
        int n = q0 + rq + qs;
        if (og < KNBR) sidx[qs][og] = idx[n * KNBR + og];
        __syncthreads();
        float uo = uv[(size_t)n * twoO + og];
        float mx = NEGINF, mn = -NEGINF;
#pragma unroll
        for (int kk = 0; kk < KNBR; ++kk) {
            float h = uo + uv[(size_t)sidx[qs][kk] * twoO + O + og];
            s += h;
            s2 = fmaf(h, h, s2);
            mx = fmaxf(mx, h);
            mn = fminf(mn, h);
        }
        hmax[(size_t)n * O + og] = mx;
        hmin[(size_t)n * O + og] = mn;
        __syncthreads();
    }

    sred[tid] = s; sred2[tid] = s2;
    __syncthreads();
    if (qs == 0) {
        for (int g = 1; g < grp; ++g) { s += sred[g * O + og]; s2 += sred2[g * O + og]; }
        psum[blockIdx.x * O + og] = s;
        psq [blockIdx.x * O + og] = s2;
    }
}

__global__ void finalize_kernel(const float* __restrict__ psum, const float* __restrict__ psq,
                                const float* __restrict__ gamma, const float* __restrict__ beta,
                                float* __restrict__ scale, float* __restrict__ shift,
                                int O, int nblocks)
{
    int o = threadIdx.x;
    float s = 0.f, s2 = 0.f;
    for (int i = 0; i < nblocks; ++i) { s += psum[i * O + o]; s2 += psq[i * O + o]; }
    const float cnt = (float)EDGE_CNT;
    float mean = s / cnt;
    float var  = s2 / cnt - mean * mean;
    float sc = gamma[o] * rsqrtf(var + 1e-5f);
    scale[o] = sc;
    shift[o] = beta[o] - mean * sc;
}

// ---------------- elementwise BN + relu on precomputed extrema ----------------
__global__ void apply_kernel(const float* __restrict__ hmax, const float* __restrict__ hmin,
                             const float* __restrict__ scale, const float* __restrict__ shift,
                             float* __restrict__ xout, int O)
{
    int i = blockIdx.x * 256 + threadIdx.x;
    if (i >= NPTS * O) return;
    int o = i & (O - 1);
    float sc = scale[o], sh = shift[o];
    float h = (sc >= 0.f) ? hmax[i] : hmin[i];
    xout[i] = fmaxf(fmaf(sc, h, sh), 0.f);
}

// ---------------- global pool + fc ----------------
__global__ void pool_kernel(const float* __restrict__ x3, float* __restrict__ pool)
{
    int b = blockIdx.x, o = threadIdx.x;
    const float* p = x3 + (size_t)b * NN * 256 + o;
    float mx = NEGINF;
    for (int n = 0; n < NN; ++n) mx = fmaxf(mx, p[(size_t)n * 256]);
    pool[b * 256 + o] = mx;
}

__global__ void fc_kernel(const float* __restrict__ pool, const float* __restrict__ wo,
                          const float* __restrict__ bo, float* __restrict__ out)
{
    int b = blockIdx.x, j = threadIdx.x;
    __shared__ float ps[256];
    ps[j] = pool[b * 256 + j];
    __syncthreads();
    float s = bo[j];
    for (int o = 0; o < 256; ++o) s = fmaf(ps[o], wo[j * 256 + o], s);
    out[b * 256 + j] = s;
}

// ---------------- host driver ----------------
static void run_layer(const float* xin, int C, int O,
                      const float* w, const float* b, const float* g, const float* be,
                      float* xout,
                      float* D, float* xxp, int* idxp, float* uv,
                      __nv_bfloat16* Ac, __nv_bfloat16* Bc, __nv_bfloat16* Wp,
                      float* psum, float* psq, float* scale, float* shift,
                      float* hmax, float* hmin)
{
    int twoO = 2 * O;
    int Kp = (3 * C + 63) & ~63;

    long long cat_total = (long long)NPTS * Kp;
    prep_cat<<<(unsigned)((cat_total + 255) / 256), 256>>>(xin, Ac, Bc, C, Kp);
    xx_kernel<<<NPTS / 256, 256>>>(xin, xxp, C);
    wpack<<<(twoO * Kp + 255) / 256, 256>>>(w, Wp, C, O, Kp);

    size_t smem_bytes = (size_t)512 * Kp;

    // per-batch dist + topk: D (16 MB) stays L2-resident, never round-trips HBM
    for (int bb = 0; bb < BB; ++bb) {
        mma_nt<1><<<dim3(16, 16, 1), 256, smem_bytes>>>(
            Ac + (size_t)bb * NN * Kp, Bc + (size_t)bb * NN * Kp,
            xxp + bb * NN, D, Kp, NN, 0);
        topk_kernel<<<NN, 256>>>(D, idxp + bb * NN * KNBR, bb * NN);
    }

    mma_nt<0><<<dim3(twoO / 128, NPTS / 128, 1), 256, smem_bytes>>>(Ac, Wp, b, uv, Kp, twoO, O);

    stats_kernel<<<512, 256>>>(uv, idxp, psum, psq, hmax, hmin, O);
    finalize_kernel<<<1, O>>>(psum, psq, g, be, scale, shift, O, 512);
    apply_kernel<<<(NPTS * O + 255) / 256, 256>>>(hmax, hmin, scale, shift, xout, O);
}

extern "C" void kernel_launch(void* const* d_in, const int* in_sizes, int n_in,
                              void* d_out, int out_size)
{
    (void)in_sizes; (void)n_in; (void)out_size;
    const float* x   = (const float*)d_in[0];
    const float* w1  = (const float*)d_in[1];
    const float* b1  = (const float*)d_in[2];
    const float* g1  = (const float*)d_in[3];
    const float* be1 = (const float*)d_in[4];
    const float* w2  = (const float*)d_in[5];
    const float* b2  = (const float*)d_in[6];
    const float* g2  = (const float*)d_in[7];
    const float* be2 = (const float*)d_in[8];
    const float* w3  = (const float*)d_in[9];
    const float* b3  = (const float*)d_in[10];
    const float* g3  = (const float*)d_in[11];
    const float* be3 = (const float*)d_in[12];
    const float* wo  = (const float*)d_in[13];
    const float* bo  = (const float*)d_in[14];

    cudaFuncSetAttribute(mma_nt<0>, cudaFuncAttributeMaxDynamicSharedMemorySize, 512 * KPMAX);
    cudaFuncSetAttribute(mma_nt<1>, cudaFuncAttributeMaxDynamicSharedMemorySize, 512 * KPMAX);

    float *D, *xxp, *uv, *xa, *xb, *xc, *psum, *psq, *scale, *shift, *pl, *hmax, *hmin;
    __nv_bfloat16 *Ac, *Bc, *Wp;
    int* idxp;
    cudaGetSymbolAddress((void**)&D,     g_D);
    cudaGetSymbolAddress((void**)&idxp,  g_idx);
    cudaGetSymbolAddress((void**)&xxp,   g_xx);
    cudaGetSymbolAddress((void**)&uv,    g_uv);
    cudaGetSymbolAddress((void**)&xa,    g_xa);
    cudaGetSymbolAddress((void**)&xb,    g_xb);
    cudaGetSymbolAddress((void**)&xc,    g_xc);
    cudaGetSymbolAddress((void**)&psum,  g_psum);
    cudaGetSymbolAddress((void**)&psq,   g_psq);
    cudaGetSymbolAddress((void**)&scale, g_scale);
    cudaGetSymbolAddress((void**)&shift, g_shift);
    cudaGetSymbolAddress((void**)&pl,    g_pool);
    cudaGetSymbolAddress((void**)&Ac,    g_Acat);
    cudaGetSymbolAddress((void**)&Bc,    g_Bcat);
    cudaGetSymbolAddress((void**)&Wp,    g_Wp);
    cudaGetSymbolAddress((void**)&hmax,  g_hmax);
    cudaGetSymbolAddress((void**)&hmin,  g_hmin);

    run_layer(x,  3,   64,  w1, b1, g1, be1, xa, D, xxp, idxp, uv, Ac, Bc, Wp, psum, psq, scale, shift, hmax, hmin);
    run_layer(xa, 64,  128, w2, b2, g2, be2, xb, D, xxp, idxp, uv, Ac, Bc, Wp, psum, psq, scale, shift, hmax, hmin);
    run_layer(xb, 128, 256, w3, b3, g3, be3, xc, D, xxp, idxp, uv, Ac, Bc, Wp, psum, psq, scale, shift, hmax, hmin);

    pool_kernel<<<BB, 256>>>(xc, pl);
    fc_kernel<<<BB, 256>>>(pl, wo, bo, (float*)d_out);
}

// round 14
// speedup vs baseline: 2.0210x; 2.0210x over previous
#include <cuda_runtime.h>
#include <cuda_bf16.h>
#include <cstdint>

// ---------------- problem constants ----------------
#define BB 8
#define NN 2048
#define KNBR 20
#define NPTS (BB*NN)          // 16384
#define EDGE_CNT (NPTS*KNBR)  // 327680
#define KPMAX 384             // max padded split-K (3*128)
#define NEGINF __int_as_float(0xff800000)

// ---------------- device scratch (static, no runtime alloc) ----------------
__device__ float g_D[(size_t)BB*NN*NN];        // 134 MB pairwise scores
__device__ int   g_idx[NPTS*KNBR];
__device__ float g_xx[NPTS];
__device__ __nv_bfloat16 g_Acat[(size_t)NPTS*KPMAX];  // [xh|xh|xl]
__device__ __nv_bfloat16 g_Bcat[(size_t)NPTS*KPMAX];  // [xh|xl|xh]
__device__ __nv_bfloat16 g_Wp[(size_t)512*KPMAX];     // [Wh|Wl|Wh] per out-channel
__device__ float g_uv[(size_t)NPTS*512];
__device__ float g_hmax[(size_t)NPTS*256];
__device__ float g_hmin[(size_t)NPTS*256];
__device__ float g_xa[(size_t)NPTS*64];
__device__ float g_xb[(size_t)NPTS*128];
__device__ float g_xc[(size_t)NPTS*256];
__device__ float g_psum[512*256];
__device__ float g_psq [512*256];
__device__ float g_scale[256];
__device__ float g_shift[256];
__device__ float g_pool[BB*256];

// ---------------- hi/lo split pack of activations ----------------
__global__ void prep_cat(const float* __restrict__ x, __nv_bfloat16* __restrict__ Ac,
                         __nv_bfloat16* __restrict__ Bc, int C, int Kp)
{
    long long i = (long long)blockIdx.x * 256 + threadIdx.x;
    long long total = (long long)NPTS * Kp;
    if (i >= total) return;
    int n = (int)(i / Kp);
    int q = (int)(i - (long long)n * Kp);
    __nv_bfloat16 a, b;
    if (q < 3 * C) {
        int seg = q / C, c = q - seg * C;
        float v = x[(size_t)n * C + c];
        __nv_bfloat16 hi = __float2bfloat16(v);
        __nv_bfloat16 lo = __float2bfloat16(v - __bfloat162float(hi));
        if (seg == 0)      { a = hi; b = hi; }
        else if (seg == 1) { a = hi; b = lo; }
        else               { a = lo; b = hi; }
    } else {
        a = __float2bfloat16(0.f); b = a;
    }
    Ac[i] = a; Bc[i] = b;
}

// ---------------- weight pack: Wp[j][q], segs [Wh|Wl|Wh] of (W1-W2 | W2) ----------------
__global__ void wpack(const float* __restrict__ w, __nv_bfloat16* __restrict__ Bp,
                      int C, int O, int Kp)
{
    int i = blockIdx.x * 256 + threadIdx.x;
    if (i >= 2 * O * Kp) return;
    int j = i / Kp, q = i - j * Kp;
    __nv_bfloat16 outv = __float2bfloat16(0.f);
    if (q < 3 * C) {
        int seg = q / C, c = q - seg * C;
        float base = (j < O) ? (w[j * 2 * C + c] - w[j * 2 * C + C + c])
                             : w[(j - O) * 2 * C + C + c];
        __nv_bfloat16 hi = __float2bfloat16(base);
        outv = (seg == 1) ? __float2bfloat16(base - __bfloat162float(hi)) : hi;
    }
    Bp[i] = outv;
}

// ---------------- squared norms (exact fp32) ----------------
__global__ void xx_kernel(const float* __restrict__ x, float* __restrict__ xx, int C)
{
    int n = blockIdx.x * 256 + threadIdx.x;
    if (n >= NPTS) return;
    const float* p = x + (size_t)n * C;
    float s = 0.f;
    for (int c = 0; c < C; ++c) s = fmaf(p[c], p[c], s);
    xx[n] = s;
}

// ---------------- HMMA helpers ----------------
__device__ __forceinline__ uint32_t smem_u32(const void* p){
    uint32_t r; asm("{ .reg .u64 t; cvta.to.shared.u64 t, %1; cvt.u32.u64 %0, t; }" : "=r"(r) : "l"(p)); return r;
}
__device__ __forceinline__ void ldm_x4(uint32_t& r0, uint32_t& r1, uint32_t& r2, uint32_t& r3, uint32_t a){
    asm volatile("ldmatrix.sync.aligned.m8n8.x4.shared.b16 {%0,%1,%2,%3}, [%4];"
                 : "=r"(r0), "=r"(r1), "=r"(r2), "=r"(r3) : "r"(a));
}
__device__ __forceinline__ void ldm_x2(uint32_t& r0, uint32_t& r1, uint32_t a){
    asm volatile("ldmatrix.sync.aligned.m8n8.x2.shared.b16 {%0,%1}, [%2];"
                 : "=r"(r0), "=r"(r1) : "r"(a));
}
__device__ __forceinline__ void mma16816(float* c, uint32_t a0, uint32_t a1, uint32_t a2, uint32_t a3,
                                         uint32_t b0, uint32_t b1){
    asm volatile("mma.sync.aligned.m16n8k16.row.col.f32.bf16.bf16.f32 "
                 "{%0,%1,%2,%3}, {%4,%5,%6,%7}, {%8,%9}, {%0,%1,%2,%3};"
                 : "+f"(c[0]), "+f"(c[1]), "+f"(c[2]), "+f"(c[3])
                 : "r"(a0), "r"(a1), "r"(a2), "r"(a3), "r"(b0), "r"(b1));
}
__device__ __forceinline__ uint32_t swadr(uint32_t base, int r, int c, int CPR){
    int sc = (c & ~7) | ((c ^ r) & 7);
    return base + (uint32_t)((r * CPR + sc) << 4);
}

// ---------------- HMMA GEMM-NT, 128x128 CTA tile, full-K resident, direct register stores ----------------
// MODE 1 (dist): Out = 2*acc - aux[col]  (batched over blockIdx.z)
// MODE 0 (uv):   Out = acc + (col<Obias ? aux[col] : 0)
template<int MODE>
__global__ __launch_bounds__(256, 2)
void mma_nt(const __nv_bfloat16* __restrict__ A, const __nv_bfloat16* __restrict__ Bm,
            const float* __restrict__ aux, float* __restrict__ Out,
            int Kp, int ldOut, int Obias)
{
    extern __shared__ char smem[];
    __shared__ float scol[128];

    const int tid = threadIdx.x, wid = tid >> 5, lane = tid & 31;
    const int colBase = blockIdx.x * 128, rowBase = blockIdx.y * 128, b = blockIdx.z;
    const int CPR = Kp >> 3;

    char* smA = smem;
    char* smB = smem + (size_t)256 * Kp;
    const uint32_t uA = smem_u32(smA), uB = smem_u32(smB);

    if (tid < 128) {
        if (MODE == 1) scol[tid] = aux[b * NN + colBase + tid];
        else { int c = colBase + tid; scol[tid] = (c < Obias) ? aux[c] : 0.f; }
    }

    const __nv_bfloat16* gA = A + (size_t)((MODE == 1 ? b * NN : 0) + rowBase) * Kp;
    const __nv_bfloat16* gB = Bm + (size_t)((MODE == 1 ? b * NN : 0) + colBase) * Kp;
    int nchunks = 128 * CPR;
    for (int i = tid; i < nchunks; i += 256) {
        int r = i / CPR, c = i - r * CPR;
        uint32_t off = (uint32_t)((r * CPR + ((c & ~7) | ((c ^ r) & 7))) << 4);
        uint4 va = *reinterpret_cast<const uint4*>(gA + (size_t)r * Kp + c * 8);
        uint4 vb = *reinterpret_cast<const uint4*>(gB + (size_t)r * Kp + c * 8);
        *reinterpret_cast<uint4*>(smA + off) = va;
        *reinterpret_cast<uint4*>(smB + off) = vb;
    }
    __syncthreads();

    const int wm = wid & 1, wn = wid >> 1;
    const int mW = wm * 64, nW = wn * 32;

    float acc[4][4][4];
#pragma unroll
    for (int i = 0; i < 4; ++i)
#pragma unroll
        for (int j = 0; j < 4; ++j)
#pragma unroll
            for (int q = 0; q < 4; ++q) acc[i][j][q] = 0.f;

    const int aRow = lane & 15, aCH = lane >> 4;
    const int bRow = lane & 7,  bCH = (lane >> 3) & 1;

    for (int k0 = 0; k0 < Kp; k0 += 16) {
        int cbase = k0 >> 3;
        uint32_t a0[4], a1[4], a2[4], a3[4];
#pragma unroll
        for (int mi = 0; mi < 4; ++mi) {
            int r = mW + mi * 16 + aRow;
            ldm_x4(a0[mi], a1[mi], a2[mi], a3[mi], swadr(uA, r, cbase + aCH, CPR));
        }
        uint32_t b0[4], b1[4];
#pragma unroll
        for (int ni = 0; ni < 4; ++ni) {
            int r = nW + ni * 8 + bRow;
            ldm_x2(b0[ni], b1[ni], swadr(uB, r, cbase + bCH, CPR));
        }
#pragma unroll
        for (int mi = 0; mi < 4; ++mi)
#pragma unroll
            for (int ni = 0; ni < 4; ++ni)
                mma16816(acc[mi][ni], a0[mi], a1[mi], a2[mi], a3[mi], b0[ni], b1[ni]);
    }

    // direct register epilogue: 4-lane groups write 32B-contiguous float2s
    const int tq = lane >> 2, tr = lane & 3;
    float* Ob = Out + (MODE == 1 ? (size_t)b * NN * NN : (size_t)0);
#pragma unroll
    for (int mi = 0; mi < 4; ++mi) {
#pragma unroll
        for (int q2 = 0; q2 < 2; ++q2) {
            int row = rowBase + mW + mi * 16 + tq + q2 * 8;
            float* dst = Ob + (size_t)row * ldOut + colBase + nW + tr * 2;
#pragma unroll
            for (int ni = 0; ni < 4; ++ni) {
                int cl = nW + ni * 8 + tr * 2;
                float2 v;
                if (MODE == 1) {
                    v.x = 2.f * acc[mi][ni][2 * q2 + 0] - scol[cl];
                    v.y = 2.f * acc[mi][ni][2 * q2 + 1] - scol[cl + 1];
                } else {
                    v.x = acc[mi][ni][2 * q2 + 0] + scol[cl];
                    v.y = acc[mi][ni][2 * q2 + 1] + scol[cl + 1];
                }
                *reinterpret_cast<float2*>(dst + ni * 8) = v;
            }
        }
    }
}

// ---------------- radix-select top-k: exact top-20 set per row, 4x8-bit passes ----------------
__global__ __launch_bounds__(256, 8)
void topk_radix(const float* __restrict__ D, int* __restrict__ out)
{
    __shared__ unsigned hist[256];
    __shared__ unsigned s_bin, s_above;
    __shared__ unsigned cgt, ctie;
    __shared__ int tlist[64];

    const int q = blockIdx.x, tid = threadIdx.x;
    const int gbase = (q >> 11) << 11;
    const float* row = D + (size_t)q * NN;

    // order-preserving float->uint transform
    unsigned u[8];
#pragma unroll
    for (int j = 0; j < 8; ++j) {
        unsigned bbits = __float_as_uint(row[tid + j * 256]);
        u[j] = (bbits & 0x80000000u) ? ~bbits : (bbits | 0x80000000u);
    }

    unsigned prefix = 0, needed = KNBR;

#pragma unroll
    for (int pass = 0; pass < 4; ++pass) {
        const int shift = 24 - 8 * pass;
        hist[tid] = 0;
        __syncthreads();
#pragma unroll
        for (int j = 0; j < 8; ++j) {
            bool act = (pass == 0) || ((u[j] >> (shift + 8)) == prefix);
            if (act) atomicAdd(&hist[(u[j] >> shift) & 255u], 1u);
        }
        __syncthreads();

        // warp 0: find bin b with above(b) < needed <= above(b)+hist[b]
        // (shfl executed UNCONDITIONALLY by all 32 lanes; only the add is predicated)
        if (tid < 32) {
            unsigned h[8], lsum = 0;
#pragma unroll
            for (int t = 0; t < 8; ++t) { h[t] = hist[tid * 8 + t]; lsum += h[t]; }

            // inclusive suffix-sum over lanes: incl = sum_{m>=tid} lsum_m
            unsigned incl = lsum;
#pragma unroll
            for (int off = 1; off < 32; off <<= 1) {
                unsigned o = __shfl_down_sync(0xffffffffu, incl, off);
                incl += (tid + off < 32) ? o : 0u;
            }
            unsigned above_lane = incl - lsum;   // counts in lanes above (higher bins)

            unsigned running = above_lane;
#pragma unroll
            for (int t = 7; t >= 0; --t) {
                unsigned binv = (unsigned)(tid * 8 + t);
                if (running < needed && needed <= running + h[t]) {
                    s_bin = binv; s_above = running;
                }
                running += h[t];
            }
        }
        __syncthreads();
        needed -= s_above;
        prefix = (prefix << 8) | s_bin;
        __syncthreads();
    }

    // threshold = prefix (exact uint); take all u>thr plus 'needed' lowest-index ties
    if (tid == 0) { cgt = 0; ctie = 0; }
    __syncthreads();

    int* orow = out + q * KNBR;
#pragma unroll
    for (int j = 0; j < 8; ++j) {
        int col = tid + j * 256;
        if (u[j] > prefix) {
            unsigned p = atomicAdd(&cgt, 1u);
            if (p < KNBR) orow[p] = gbase + col;
        } else if (u[j] == prefix) {
            unsigned t = atomicAdd(&ctie, 1u);
            if (t < 64) tlist[t] = col;
        }
    }
    __syncthreads();

    if (tid == 0) {
        int m = (ctie < 64u) ? (int)ctie : 64;
        for (int a = 1; a < m; ++a) {
            int key = tlist[a]; int bpos = a - 1;
            while (bpos >= 0 && tlist[bpos] > key) { tlist[bpos + 1] = tlist[bpos]; --bpos; }
            tlist[bpos + 1] = key;
        }
        unsigned base0 = cgt;
        for (unsigned i = 0; i < needed && (base0 + i) < KNBR; ++i)
            orow[base0 + i] = gbase + tlist[i];
    }
}

// ---------------- BN stats + per-(n,o) hmax/hmin over edges (single gather pass) ----------------
__global__ __launch_bounds__(256)
void stats_kernel(const float* __restrict__ uv, const int* __restrict__ idx,
                  float* __restrict__ psum, float* __restrict__ psq,
                  float* __restrict__ hmax, float* __restrict__ hmin, int O)
{
    __shared__ int sidx[4][KNBR];
    __shared__ float sred[256], sred2[256];

    const int tid = threadIdx.x;
    const int og = tid & (O - 1);
    const int qs = tid / O;
    const int grp = 256 / O;
    const int twoO = 2 * O;
    const int q0 = blockIdx.x * 32;

    float s = 0.f, s2 = 0.f;
    for (int rq = 0; rq < 32; rq += grp) {
        int n = q0 + rq + qs;
        if (og < KNBR) sidx[qs][og] = idx[n * KNBR + og];
        __syncthreads();
        float uo = uv[(size_t)n * twoO + og];
        float mx = NEGINF, mn = -NEGINF;
#pragma unroll
        for (int kk = 0; kk < KNBR; ++kk) {
            float h = uo + uv[(size_t)sidx[qs][kk] * twoO + O + og];
            s += h;
            s2 = fmaf(h, h, s2);
            mx = fmaxf(mx, h);
            mn = fminf(mn, h);
        }
        hmax[(size_t)n * O + og] = mx;
        hmin[(size_t)n * O + og] = mn;
        __syncthreads();
    }

    sred[tid] = s; sred2[tid] = s2;
    __syncthreads();
    if (qs == 0) {
        for (int g = 1; g < grp; ++g) { s += sred[g * O + og]; s2 += sred2[g * O + og]; }
        psum[blockIdx.x * O + og] = s;
        psq [blockIdx.x * O + og] = s2;
    }
}

__global__ void finalize_kernel(const float* __restrict__ psum, const float* __restrict__ psq,
                                const float* __restrict__ gamma, const float* __restrict__ beta,
                                float* __restrict__ scale, float* __restrict__ shift,
                                int O, int nblocks)
{
    int o = threadIdx.x;
    float s = 0.f, s2 = 0.f;
    for (int i = 0; i < nblocks; ++i) { s += psum[i * O + o]; s2 += psq[i * O + o]; }
    const float cnt = (float)EDGE_CNT;
    float mean = s / cnt;
    float var  = s2 / cnt - mean * mean;
    float sc = gamma[o] * rsqrtf(var + 1e-5f);
    scale[o] = sc;
    shift[o] = beta[o] - mean * sc;
}

// ---------------- elementwise BN + relu on precomputed extrema ----------------
__global__ void apply_kernel(const float* __restrict__ hmax, const float* __restrict__ hmin,
                             const float* __restrict__ scale, const float* __restrict__ shift,
                             float* __restrict__ xout, int O)
{
    int i = blockIdx.x * 256 + threadIdx.x;
    if (i >= NPTS * O) return;
    int o = i & (O - 1);
    float sc = scale[o], sh = shift[o];
    float h = (sc >= 0.f) ? hmax[i] : hmin[i];
    xout[i] = fmaxf(fmaf(sc, h, sh), 0.f);
}

// ---------------- global pool + fc ----------------
__global__ void pool_kernel(const float* __restrict__ x3, float* __restrict__ pool)
{
    int b = blockIdx.x, o = threadIdx.x;
    const float* p = x3 + (size_t)b * NN * 256 + o;
    float mx = NEGINF;
    for (int n = 0; n < NN; ++n) mx = fmaxf(mx, p[(size_t)n * 256]);
    pool[b * 256 + o] = mx;
}

__global__ void fc_kernel(const float* __restrict__ pool, const float* __restrict__ wo,
                          const float* __restrict__ bo, float* __restrict__ out)
{
    int b = blockIdx.x, j = threadIdx.x;
    __shared__ float ps[256];
    ps[j] = pool[b * 256 + j];
    __syncthreads();
    float s = bo[j];
    for (int o = 0; o < 256; ++o) s = fmaf(ps[o], wo[j * 256 + o], s);
    out[b * 256 + j] = s;
}

// ---------------- host driver ----------------
static void run_layer(const float* xin, int C, int O,
                      const float* w, const float* b, const float* g, const float* be,
                      float* xout,
                      float* D, float* xxp, int* idxp, float* uv,
                      __nv_bfloat16* Ac, __nv_bfloat16* Bc, __nv_bfloat16* Wp,
                      float* psum, float* psq, float* scale, float* shift,
                      float* hmax, float* hmin)
{
    int twoO = 2 * O;
    int Kp = (3 * C + 63) & ~63;

    long long cat_total = (long long)NPTS * Kp;
    prep_cat<<<(unsigned)((cat_total + 255) / 256), 256>>>(xin, Ac, Bc, C, Kp);
    xx_kernel<<<NPTS / 256, 256>>>(xin, xxp, C);
    wpack<<<(twoO * Kp + 255) / 256, 256>>>(w, Wp, C, O, Kp);

    size_t smem_bytes = (size_t)512 * Kp;

    mma_nt<1><<<dim3(16, 16, BB), 256, smem_bytes>>>(Ac, Bc, xxp, D, Kp, NN, 0);
    topk_radix<<<NPTS, 256>>>(D, idxp);

    mma_nt<0><<<dim3(twoO / 128, NPTS / 128, 1), 256, smem_bytes>>>(Ac, Wp, b, uv, Kp, twoO, O);

    stats_kernel<<<512, 256>>>(uv, idxp, psum, psq, hmax, hmin, O);
    finalize_kernel<<<1, O>>>(psum, psq, g, be, scale, shift, O, 512);
    apply_kernel<<<(NPTS * O + 255) / 256, 256>>>(hmax, hmin, scale, shift, xout, O);
}

extern "C" void kernel_launch(void* const* d_in, const int* in_sizes, int n_in,
                              void* d_out, int out_size)
{
    (void)in_sizes; (void)n_in; (void)out_size;
    const float* x   = (const float*)d_in[0];
    const float* w1  = (const float*)d_in[1];
    const float* b1  = (const float*)d_in[2];
    const float* g1  = (const float*)d_in[3];
    const float* be1 = (const float*)d_in[4];
    const float* w2  = (const float*)d_in[5];
    const float* b2  = (const float*)d_in[6];
    const float* g2  = (const float*)d_in[7];
    const float* be2 = (const float*)d_in[8];
    const float* w3  = (const float*)d_in[9];
    const float* b3  = (const float*)d_in[10];
    const float* g3  = (const float*)d_in[11];
    const float* be3 = (const float*)d_in[12];
    const float* wo  = (const float*)d_in[13];
    const float* bo  = (const float*)d_in[14];

    cudaFuncSetAttribute(mma_nt<0>, cudaFuncAttributeMaxDynamicSharedMemorySize, 512 * KPMAX);
    cudaFuncSetAttribute(mma_nt<1>, cudaFuncAttributeMaxDynamicSharedMemorySize, 512 * KPMAX);

    float *D, *xxp, *uv, *xa, *xb, *xc, *psum, *psq, *scale, *shift, *pl, *hmax, *hmin;
    __nv_bfloat16 *Ac, *Bc, *Wp;
    int* idxp;
    cudaGetSymbolAddress((void**)&D,     g_D);
    cudaGetSymbolAddress((void**)&idxp,  g_idx);
    cudaGetSymbolAddress((void**)&xxp,   g_xx);
    cudaGetSymbolAddress((void**)&uv,    g_uv);
    cudaGetSymbolAddress((void**)&xa,    g_xa);
    cudaGetSymbolAddress((void**)&xb,    g_xb);
    cudaGetSymbolAddress((void**)&xc,    g_xc);
    cudaGetSymbolAddress((void**)&psum,  g_psum);
    cudaGetSymbolAddress((void**)&psq,   g_psq);
    cudaGetSymbolAddress((void**)&scale, g_scale);
    cudaGetSymbolAddress((void**)&shift, g_shift);
    cudaGetSymbolAddress((void**)&pl,    g_pool);
    cudaGetSymbolAddress((void**)&Ac,    g_Acat);
    cudaGetSymbolAddress((void**)&Bc,    g_Bcat);
    cudaGetSymbolAddress((void**)&Wp,    g_Wp);
    cudaGetSymbolAddress((void**)&hmax,  g_hmax);
    cudaGetSymbolAddress((void**)&hmin,  g_hmin);

    run_layer(x,  3,   64,  w1, b1, g1, be1, xa, D, xxp, idxp, uv, Ac, Bc, Wp, psum, psq, scale, shift, hmax, hmin);
    run_layer(xa, 64,  128, w2, b2, g2, be2, xb, D, xxp, idxp, uv, Ac, Bc, Wp, psum, psq, scale, shift, hmax, hmin);
    run_layer(xb, 128, 256, w3, b3, g3, be3, xc, D, xxp, idxp, uv, Ac, Bc, Wp, psum, psq, scale, shift, hmax, hmin);

    pool_kernel<<<BB, 256>>>(xc, pl);
    fc_kernel<<<BB, 256>>>(pl, wo, bo, (float*)d_out);
}